// round 16
// baseline (speedup 1.0000x reference)
#include <cuda_runtime.h>
#include <cuda_bf16.h>
#include <math.h>
#include <stdint.h>

// ---------------------------------------------------------------------------
// Problem constants
// ---------------------------------------------------------------------------
constexpr int BATCH = 4;
constexpr int SEQ   = 2048;
constexpr int DIM   = 768;
constexpr int GDIM  = 256;
constexpr int HDIM  = 64;
constexpr int MROWS = BATCH * SEQ;   // 8192
constexpr float DT_F  = 0.05f;
constexpr float HJ_HF = 0.05f;
constexpr int MD = MROWS * DIM;

// ---------------------------------------------------------------------------
// Device scratch (no cudaMalloc allowed)
// ---------------------------------------------------------------------------
__device__ __nv_bfloat16 g_xh[MD],  g_xl[MD];
__device__ __nv_bfloat16 g_hh[MD],  g_hl[MD];
__device__ __nv_bfloat16 g_qh[3 * MD], g_ql[3 * MD];
__device__ __nv_bfloat16 g_ah[MD],  g_al[MD];
__device__ __nv_bfloat16 g_uh[MD],  g_ul[MD];
__device__ float g_u[MD];

constexpr int WT_IN   = 0;
constexpr int WT_QKV0 = WT_IN   + 768 * 768;
constexpr int WT_OW0  = WT_QKV0 + 3 * 768 * 256;
constexpr int WT_OUT  = WT_OW0  + 3 * 256 * 256;
constexpr int WT_TOTAL = WT_OUT + 768 * 768;
__device__ __nv_bfloat16 g_whi[WT_TOTAL];
__device__ __nv_bfloat16 g_wlo[WT_TOTAL];

// ---------------------------------------------------------------------------
// Helpers
// ---------------------------------------------------------------------------
__device__ __forceinline__ uint32_t smem_u32(const void* p) {
    uint32_t a;
    asm("{ .reg .u64 t; cvta.to.shared.u64 t, %1; cvt.u32.u64 %0, t; }"
        : "=r"(a) : "l"(p));
    return a;
}
__device__ __forceinline__ void split_bf(float v, __nv_bfloat16& h, __nv_bfloat16& l) {
    h = __float2bfloat16_rn(v);
    l = __float2bfloat16_rn(v - __bfloat162float(h));
}
// Fast truncation-based split: hi pair = PRMT of the two fp32 upper halves
// (exact bf16 truncation); lo pair = rn(residual) packed with one bf16x2 cvt.
__device__ __forceinline__ uint32_t packsplit(float a, float b, uint32_t& lo) {
    uint32_t ua = __float_as_uint(a), ub = __float_as_uint(b);
    uint32_t hi;
    asm("prmt.b32 %0, %1, %2, 0x7632;" : "=r"(hi) : "r"(ua), "r"(ub));
    float ra = a - __uint_as_float(ua & 0xFFFF0000u);
    float rb = b - __uint_as_float(ub & 0xFFFF0000u);
    asm("cvt.rn.bf16x2.f32 %0, %1, %2;" : "=r"(lo) : "f"(rb), "f"(ra));
    return hi;
}
__device__ __forceinline__ void ldsm_x4(uint32_t* r, uint32_t a) {
    asm volatile("ldmatrix.sync.aligned.m8n8.x4.shared.b16 {%0,%1,%2,%3}, [%4];"
        : "=r"(r[0]), "=r"(r[1]), "=r"(r[2]), "=r"(r[3]) : "r"(a));
}
__device__ __forceinline__ void ldsm_x4t(uint32_t* r, uint32_t a) {
    asm volatile("ldmatrix.sync.aligned.m8n8.x4.trans.shared.b16 {%0,%1,%2,%3}, [%4];"
        : "=r"(r[0]), "=r"(r[1]), "=r"(r[2]), "=r"(r[3]) : "r"(a));
}
__device__ __forceinline__ void mma_bf16(float* c, const uint32_t* a, const uint32_t* b) {
    asm volatile("mma.sync.aligned.m16n8k16.row.col.f32.bf16.bf16.f32 "
        "{%0,%1,%2,%3}, {%4,%5,%6,%7}, {%8,%9}, {%0,%1,%2,%3};"
        : "+f"(c[0]), "+f"(c[1]), "+f"(c[2]), "+f"(c[3])
        : "r"(a[0]), "r"(a[1]), "r"(a[2]), "r"(a[3]), "r"(b[0]), "r"(b[1]));
}
// L2-only (L1-bypass) async copy: these streams have no L1 reuse, and the
// l1tex pipe is the GEMM's binding resource (LDSM shares it).
__device__ __forceinline__ void cp_async16(uint32_t d, const void* s) {
    asm volatile("cp.async.cg.shared.global [%0], [%1], 16;" :: "r"(d), "l"(s) : "memory");
}
__device__ __forceinline__ void cp_commit() {
    asm volatile("cp.async.commit_group;" ::: "memory");
}
__device__ __forceinline__ void cp_wait0() {
    asm volatile("cp.async.wait_group 0;" ::: "memory");
}
__device__ __forceinline__ void cp_wait1() {
    asm volatile("cp.async.wait_group 1;" ::: "memory");
}

// ---------------------------------------------------------------------------
// Weight prep: all 8 weights in one launch.
// ---------------------------------------------------------------------------
struct WJobs {
    const float* W[8];
    __nv_bfloat16* hi[8];
    __nv_bfloat16* lo[8];
    int K[8];
    int N[8];
};

__global__ void wsplit_all_kernel(WJobs jobs)
{
    const int id = blockIdx.z;
    const int K = jobs.K[id], N = jobs.N[id];
    const int kb = blockIdx.y * 32;
    const int nb = blockIdx.x * 32;
    if (kb >= K || nb >= N) return;

    const float* W = jobs.W[id];
    __nv_bfloat16* Whi = jobs.hi[id];
    __nv_bfloat16* Wlo = jobs.lo[id];

    __shared__ float tile[32][33];
    const int tx = threadIdx.x;
    for (int i = threadIdx.y; i < 32; i += 8)
        tile[i][tx] = W[(size_t)(kb + i) * N + nb + tx];
    __syncthreads();
    for (int i = threadIdx.y; i < 32; i += 8) {
        float v = tile[tx][i];
        __nv_bfloat16 h, l;
        split_bf(v, h, l);
        size_t o = (size_t)(nb + i) * K + kb + tx;
        Whi[o] = h;
        Wlo[o] = l;
    }
}

__global__ void asplit_kernel(const float* __restrict__ A,
                              __nv_bfloat16* __restrict__ hi,
                              __nv_bfloat16* __restrict__ lo, int n)
{
    int i = (blockIdx.x * 256 + threadIdx.x) * 4;
    if (i >= n) return;
    float4 v = *reinterpret_cast<const float4*>(A + i);
    uint32_t lo0, lo1;
    uint32_t hi0 = packsplit(v.x, v.y, lo0);
    uint32_t hi1 = packsplit(v.z, v.w, lo1);
    *reinterpret_cast<uint2*>(hi + i) = make_uint2(hi0, hi1);
    *reinterpret_cast<uint2*>(lo + i) = make_uint2(lo0, lo1);
}

// ---------------------------------------------------------------------------
// bf16x3 HMMA GEMM (R14 config: BM=128, BN=128, BK=32, 256 threads, 2 CTAs/SM).
// qcols: output columns < qcols scaled by 0.125*log2(e) (Q pre-scale + exp2).
// ---------------------------------------------------------------------------
constexpr int GPLANE = 128 * 80;              // 10240 B per plane
constexpr int GSTAGE = 4 * GPLANE;            // Ah|Al|Bh|Bl = 40960 B
constexpr int GEMM_SMEM = 2 * GSTAGE;         // 81920 B -> 2 CTAs/SM
constexpr float QSCALE = 0.125f * 1.4426950408889634f;

struct GemmArgs {
    const __nv_bfloat16* Ah[3];
    const __nv_bfloat16* Al[3];
    int lda, K;
    const __nv_bfloat16* Bh[3];
    const __nv_bfloat16* Bl[3];
    const float* bias[3];
    float* Cf[3];
    __nv_bfloat16* Ch[3];
    __nv_bfloat16* Cl[3];
    int ldc;
    int qcols;
};

template<bool OUT_SPLIT>
__global__ __launch_bounds__(256)
void gemm_pp_kernel(GemmArgs p)
{
    extern __shared__ char smc[];
    const uint32_t sbase = smem_u32(smc);

    const int tid  = threadIdx.x;
    const int lane = tid & 31;
    const int wid  = tid >> 5;
    const int wm   = wid & 1;
    const int wn   = wid >> 1;
    const int m0 = blockIdx.y * 128;
    const int n0 = blockIdx.x * 128;
    const int z  = blockIdx.z;
    const int KT = p.K / 32;

    const __nv_bfloat16* Ah = p.Ah[z];
    const __nv_bfloat16* Al = p.Al[z];
    const __nv_bfloat16* Bh = p.Bh[z];
    const __nv_bfloat16* Bl = p.Bl[z];

    float acc[4][4][4];
    #pragma unroll
    for (int i = 0; i < 4; ++i)
        #pragma unroll
        for (int j = 0; j < 4; ++j)
            #pragma unroll
            for (int k = 0; k < 4; ++k) acc[i][j][k] = 0.f;

    auto stage = [&](int kt, int s) {
        #pragma unroll
        for (int j = 0; j < 8; ++j) {
            int cid = tid + 256 * j;
            int plane = cid >> 9;
            int idx = cid & 511;
            int row = idx >> 2;
            int ch  = idx & 3;
            const __nv_bfloat16* src;
            if      (plane == 0) src = Ah + (size_t)(m0 + row) * p.lda + kt * 32 + ch * 8;
            else if (plane == 1) src = Al + (size_t)(m0 + row) * p.lda + kt * 32 + ch * 8;
            else if (plane == 2) src = Bh + (size_t)(n0 + row) * p.K + kt * 32 + ch * 8;
            else                 src = Bl + (size_t)(n0 + row) * p.K + kt * 32 + ch * 8;
            cp_async16(sbase + s * GSTAGE + plane * GPLANE + row * 80 + ch * 16, src);
        }
    };

    const int lr16 = lane & 15;
    const int lk8  = (lane >> 4) * 8;
    const int br  = (lane & 7) + ((lane >> 4) << 3);
    const int bkl = ((lane >> 3) & 1) * 8;

    auto compute = [&](int s) {
        const uint32_t st = sbase + s * GSTAGE;
        #pragma unroll
        for (int ks = 0; ks < 32; ks += 16) {
            uint32_t bh[4][2], bl[4][2];
            #pragma unroll
            for (int pair = 0; pair < 2; ++pair) {
                uint32_t rb = st + 2 * GPLANE
                            + ((wn * 32 + pair * 16 + br) * 80) + (ks + bkl) * 2;
                uint32_t t[4], tl[4];
                ldsm_x4(t, rb);
                ldsm_x4(tl, rb + GPLANE);
                bh[pair * 2][0] = t[0];  bh[pair * 2][1] = t[1];
                bh[pair * 2 + 1][0] = t[2]; bh[pair * 2 + 1][1] = t[3];
                bl[pair * 2][0] = tl[0]; bl[pair * 2][1] = tl[1];
                bl[pair * 2 + 1][0] = tl[2]; bl[pair * 2 + 1][1] = tl[3];
            }
            #pragma unroll
            for (int mt = 0; mt < 4; ++mt) {
                uint32_t ra = st + (wm * 64 + mt * 16 + lr16) * 80 + (ks + lk8) * 2;
                uint32_t ah[4], al[4];
                ldsm_x4(ah, ra);
                ldsm_x4(al, ra + GPLANE);
                #pragma unroll
                for (int nt = 0; nt < 4; ++nt) {
                    mma_bf16(acc[mt][nt], ah, bh[nt]);
                    mma_bf16(acc[mt][nt], ah, bl[nt]);
                    mma_bf16(acc[mt][nt], al, bh[nt]);
                }
            }
        }
    };

    stage(0, 0);
    cp_commit();
    for (int kt = 0; kt < KT; ++kt) {
        const int s = kt & 1;
        const bool more = kt + 1 < KT;
        if (more) {
            stage(kt + 1, s ^ 1);
            cp_commit();
            cp_wait1();
        } else {
            cp_wait0();
        }
        __syncthreads();
        compute(s);
        __syncthreads();
    }

    #pragma unroll
    for (int mt = 0; mt < 4; ++mt) {
        int r0 = m0 + wm * 64 + mt * 16 + (lane >> 2);
        #pragma unroll
        for (int nt = 0; nt < 4; ++nt) {
            int col = n0 + wn * 32 + nt * 8 + (lane & 3) * 2;
            float qs = (col < p.qcols) ? QSCALE : 1.0f;
            float2 bv = *reinterpret_cast<const float2*>(p.bias[z] + col);
            float c00 = (acc[mt][nt][0] + bv.x) * qs, c01 = (acc[mt][nt][1] + bv.y) * qs;
            float c10 = (acc[mt][nt][2] + bv.x) * qs, c11 = (acc[mt][nt][3] + bv.y) * qs;
            if (OUT_SPLIT) {
                uint32_t lo0, lo1;
                uint32_t hi0 = packsplit(c00, c01, lo0);
                uint32_t hi1 = packsplit(c10, c11, lo1);
                __nv_bfloat16* Ch = p.Ch[z];
                __nv_bfloat16* Cl = p.Cl[z];
                *reinterpret_cast<uint32_t*>(Ch + (size_t)r0 * p.ldc + col) = hi0;
                *reinterpret_cast<uint32_t*>(Cl + (size_t)r0 * p.ldc + col) = lo0;
                *reinterpret_cast<uint32_t*>(Ch + (size_t)(r0 + 8) * p.ldc + col) = hi1;
                *reinterpret_cast<uint32_t*>(Cl + (size_t)(r0 + 8) * p.ldc + col) = lo1;
            } else {
                float* Cf = p.Cf[z];
                *reinterpret_cast<float2*>(Cf + (size_t)r0 * p.ldc + col) =
                    make_float2(c00, c01);
                *reinterpret_cast<float2*>(Cf + (size_t)(r0 + 8) * p.ldc + col) =
                    make_float2(c10, c11);
            }
        }
    }
}

// ---------------------------------------------------------------------------
// Tensor-core flash attention: Q tile 128, KV tile 64, three-stage pipeline
// (Q SMEM region recycled as the 3rd KV buffer once Q-fragments are in regs).
// jt_max = 2*qt+1. Commit only real transfers; wait1 while a successor
// data-group is in flight (jt < jt_max), else wait0. exp2-domain softmax.
// ---------------------------------------------------------------------------
constexpr int AP = 72;
constexpr int AQL = 18432;
constexpr int AKV0 = 36864, AKVS = 36864;
constexpr int ATT_SMEM = AKV0 + 2 * AKVS;   // 110592 -> 2 CTAs/SM

__global__ __launch_bounds__(256)
void attn_tc_kernel(const __nv_bfloat16* __restrict__ qkvh,
                    const __nv_bfloat16* __restrict__ qkvl,
                    __nv_bfloat16* __restrict__ attnh,
                    __nv_bfloat16* __restrict__ attnl)
{
    extern __shared__ char smb[];
    const uint32_t S = smem_u32(smb);

    const int tid  = threadIdx.x;
    const int lane = tid & 31;
    const int w    = tid >> 5;
    const int qt = gridDim.x - 1 - blockIdx.x;   // heavy blocks first
    const int bh_ = blockIdx.y;
    const int g  = blockIdx.z;
    const int b  = bh_ >> 2;
    const int h  = bh_ & 3;
    const int q0 = qt * 128;
    const int jt_max = 2 * qt + 1;

    const size_t gb = (size_t)g * MROWS * DIM + (size_t)b * SEQ * DIM;
    const __nv_bfloat16* ph = qkvh + gb;
    const __nv_bfloat16* pl = qkvl + gb;
    const int qo = h * HDIM;
    const int ko = GDIM + h * HDIM;
    const int vo = 2 * GDIM + h * HDIM;

    auto buf_base = [&](int jt) -> uint32_t {
        int bi = jt % 3;
        return (bi == 2) ? S : (S + AKV0 + bi * AKVS);
    };

    auto stage_kv = [&](int jt) {
        const int j0 = jt * 64;
        const uint32_t B = buf_base(jt);
        #pragma unroll
        for (int j = 0; j < 8; ++j) {
            int cid = tid + 256 * j;
            int plane = cid >> 9;          // 0 Kh, 1 Kl, 2 Vh, 3 Vl
            int idx = cid & 511;
            int row = idx >> 3;
            int ch  = idx & 7;
            const __nv_bfloat16* bp = (plane & 1) ? pl : ph;
            int co = (plane >> 1) ? vo : ko;
            cp_async16(B + plane * 9216 + (row * AP + ch * 8) * 2,
                       bp + (size_t)(j0 + row) * DIM + co + ch * 8);
        }
    };

    // Q stage into buffer-2 area (consumed into registers at jt=0)
    #pragma unroll
    for (int j = 0; j < 8; ++j) {
        int cid = tid + 256 * j;
        int plane = cid >> 10;
        int idx = cid & 1023;
        int row = idx >> 3;
        int ch  = idx & 7;
        const __nv_bfloat16* bp = plane ? pl : ph;
        cp_async16(S + plane * AQL + (row * AP + ch * 8) * 2,
                   bp + (size_t)(q0 + row) * DIM + qo + ch * 8);
    }
    stage_kv(0);
    cp_commit();                                   // group: Q + KV0
    if (jt_max >= 1) { stage_kv(1); cp_commit(); } // group: KV1

    uint32_t aqh[4][4], aql[4][4];

    float m_[2] = {-1e30f, -1e30f};
    float l_[2] = {0.f, 0.f};
    float oacc[8][4];
    #pragma unroll
    for (int j = 0; j < 8; ++j)
        #pragma unroll
        for (int r = 0; r < 4; ++r) oacc[j][r] = 0.f;

    const int lr16 = lane & 15;
    const int lk8  = (lane >> 4) * 8;
    const int br   = (lane & 7) + ((lane >> 4) << 3);
    const int bkl  = ((lane >> 3) & 1) * 8;

    for (int jt = 0; jt <= jt_max; ++jt) {
        if (jt < jt_max) cp_wait1(); else cp_wait0();
        __syncthreads();

        if (jt == 0) {
            const int ar = w * 16 + lr16;
            #pragma unroll
            for (int ks = 0; ks < 4; ++ks) {
                uint32_t a = S + (ar * AP + ks * 16 + lk8) * 2;
                ldsm_x4(aqh[ks], a);
                ldsm_x4(aql[ks], a + AQL);
            }
            __syncthreads();
        }

        if (jt + 2 <= jt_max) { stage_kv(jt + 2); cp_commit(); }

        const int j0 = jt * 64;
        if (j0 <= q0 + w * 16 + 15) {
            const uint32_t KB = buf_base(jt);

            float sacc[8][4];
            #pragma unroll
            for (int j = 0; j < 8; ++j)
                #pragma unroll
                for (int r = 0; r < 4; ++r) sacc[j][r] = 0.f;

            #pragma unroll
            for (int ks = 0; ks < 4; ++ks) {
                uint32_t bhf[4][4], blf[4][4];
                #pragma unroll
                for (int np = 0; np < 4; ++np) {
                    uint32_t a = KB + ((np * 16 + br) * AP + ks * 16 + bkl) * 2;
                    ldsm_x4(bhf[np], a);
                    ldsm_x4(blf[np], a + 9216);
                }
                #pragma unroll
                for (int np = 0; np < 4; ++np) {
                    mma_bf16(sacc[2 * np],     aqh[ks], &bhf[np][0]);
                    mma_bf16(sacc[2 * np + 1], aqh[ks], &bhf[np][2]);
                }
                #pragma unroll
                for (int np = 0; np < 4; ++np) {
                    mma_bf16(sacc[2 * np],     aqh[ks], &blf[np][0]);
                    mma_bf16(sacc[2 * np + 1], aqh[ks], &blf[np][2]);
                }
                #pragma unroll
                for (int np = 0; np < 4; ++np) {
                    mma_bf16(sacc[2 * np],     aql[ks], &bhf[np][0]);
                    mma_bf16(sacc[2 * np + 1], aql[ks], &bhf[np][2]);
                }
            }

            const int rbase = q0 + w * 16 + (lane >> 2);
            const int cbase = (lane & 3) * 2;
            if (j0 + 63 > q0 + w * 16) {
                #pragma unroll
                for (int j = 0; j < 8; ++j)
                    #pragma unroll
                    for (int rw = 0; rw < 2; ++rw)
                        #pragma unroll
                        for (int c = 0; c < 2; ++c)
                            if (j0 + j * 8 + cbase + c > rbase + rw * 8)
                                sacc[j][rw * 2 + c] = -1e30f;
            }

            #pragma unroll
            for (int rw = 0; rw < 2; ++rw) {
                float rm = -1e30f;
                #pragma unroll
                for (int j = 0; j < 8; ++j) {
                    rm = fmaxf(rm, sacc[j][rw * 2]);
                    rm = fmaxf(rm, sacc[j][rw * 2 + 1]);
                }
                rm = fmaxf(rm, __shfl_xor_sync(0xffffffffu, rm, 1));
                rm = fmaxf(rm, __shfl_xor_sync(0xffffffffu, rm, 2));
                const float mnew  = fmaxf(m_[rw], rm);
                const float alpha = exp2f(m_[rw] - mnew);
                m_[rw] = mnew;
                float rs = 0.f;
                #pragma unroll
                for (int j = 0; j < 8; ++j) {
                    float p0 = exp2f(sacc[j][rw * 2]     - mnew);
                    float p1 = exp2f(sacc[j][rw * 2 + 1] - mnew);
                    sacc[j][rw * 2]     = p0;
                    sacc[j][rw * 2 + 1] = p1;
                    rs += p0 + p1;
                }
                rs += __shfl_xor_sync(0xffffffffu, rs, 1);
                rs += __shfl_xor_sync(0xffffffffu, rs, 2);
                l_[rw] = l_[rw] * alpha + rs;
                #pragma unroll
                for (int j = 0; j < 8; ++j) {
                    oacc[j][rw * 2]     *= alpha;
                    oacc[j][rw * 2 + 1] *= alpha;
                }
            }

            uint32_t ph4[4][4], pl4[4][4];
            #pragma unroll
            for (int u = 0; u < 4; ++u) {
                ph4[u][0] = packsplit(sacc[2 * u][0],     sacc[2 * u][1],     pl4[u][0]);
                ph4[u][1] = packsplit(sacc[2 * u][2],     sacc[2 * u][3],     pl4[u][1]);
                ph4[u][2] = packsplit(sacc[2 * u + 1][0], sacc[2 * u + 1][1], pl4[u][2]);
                ph4[u][3] = packsplit(sacc[2 * u + 1][2], sacc[2 * u + 1][3], pl4[u][3]);
            }

            {
                const int vk = ((lane >> 3) & 1) * 8 + (lane & 7);
                const int vn = (lane >> 4) * 8;
                const uint32_t VB = KB + 18432;
                #pragma unroll
                for (int u = 0; u < 4; ++u) {
                    uint32_t bvh[4][4], bvl[4][4];
                    #pragma unroll
                    for (int np = 0; np < 4; ++np) {
                        uint32_t a = VB + ((u * 16 + vk) * AP + np * 16 + vn) * 2;
                        ldsm_x4t(bvh[np], a);
                        ldsm_x4t(bvl[np], a + 9216);
                    }
                    #pragma unroll
                    for (int np = 0; np < 4; ++np) {
                        mma_bf16(oacc[2 * np],     ph4[u], &bvh[np][0]);
                        mma_bf16(oacc[2 * np + 1], ph4[u], &bvh[np][2]);
                    }
                    #pragma unroll
                    for (int np = 0; np < 4; ++np) {
                        mma_bf16(oacc[2 * np],     ph4[u], &bvl[np][0]);
                        mma_bf16(oacc[2 * np + 1], ph4[u], &bvl[np][2]);
                    }
                    #pragma unroll
                    for (int np = 0; np < 4; ++np) {
                        mma_bf16(oacc[2 * np],     pl4[u], &bvh[np][0]);
                        mma_bf16(oacc[2 * np + 1], pl4[u], &bvh[np][2]);
                    }
                }
            }
        }
    }

    #pragma unroll
    for (int rw = 0; rw < 2; ++rw) {
        const float inv = 1.0f / l_[rw];
        const size_t row = (size_t)b * SEQ + q0 + w * 16 + (lane >> 2) + rw * 8;
        const size_t off = row * DIM + g * GDIM + h * HDIM + (lane & 3) * 2;
        #pragma unroll
        for (int j = 0; j < 8; ++j) {
            uint32_t lo;
            uint32_t hi = packsplit(oacc[j][rw * 2] * inv,
                                    oacc[j][rw * 2 + 1] * inv, lo);
            *reinterpret_cast<uint32_t*>(attnh + off + j * 8) = hi;
            *reinterpret_cast<uint32_t*>(attnl + off + j * 8) = lo;
        }
    }
}

// ---------------------------------------------------------------------------
// Fused PDE kernel, 4 channels per block (float4 lanes), blockIdx.y = equation.
// ---------------------------------------------------------------------------
constexpr int PDE_SMEM = 3 * SEQ * 16;

__global__ void pde_all_kernel(const float* __restrict__ u,
                               __nv_bfloat16* __restrict__ uh,
                               __nv_bfloat16* __restrict__ ul)
{
    const int eq = blockIdx.y;
    const int b  = blockIdx.x >> 6;
    const int c4 = blockIdx.x & 63;
    const size_t base = (size_t)b * SEQ * DIM + eq * GDIM + c4 * 4;

    extern __shared__ float4 sp[];
    float4* su = sp;
    float4* sw = sp + SEQ;
    float4* sf = sp + 2 * SEQ;
    const int tid = threadIdx.x;
    const float4 z4 = make_float4(0.f, 0.f, 0.f, 0.f);

    for (int t = tid; t < SEQ; t += 256) {
        su[t] = *reinterpret_cast<const float4*>(u + base + (size_t)t * DIM);
        sw[t] = z4;
    }
    __syncthreads();

    #define AT(arr, t) ((t) >= 0 && (t) < SEQ ? arr[t] : z4)

    if (eq == 0) {
        for (int step = 0; step < 3; ++step) {
            float4 dw[8];
            #pragma unroll
            for (int i = 0; i < 8; ++i) {
                int t = tid + i * 256;
                float4 um = AT(su, t - 1), up = AT(su, t + 1), uc = su[t];
                dw[i].x = DT_F * ((um.x - 2.f * uc.x + up.x) - sinf(uc.x));
                dw[i].y = DT_F * ((um.y - 2.f * uc.y + up.y) - sinf(uc.y));
                dw[i].z = DT_F * ((um.z - 2.f * uc.z + up.z) - sinf(uc.z));
                dw[i].w = DT_F * ((um.w - 2.f * uc.w + up.w) - sinf(uc.w));
            }
            __syncthreads();
            #pragma unroll
            for (int i = 0; i < 8; ++i) {
                int t = tid + i * 256;
                float4 wv = sw[t], uv = su[t];
                wv.x += dw[i].x; wv.y += dw[i].y; wv.z += dw[i].z; wv.w += dw[i].w;
                uv.x += DT_F * wv.x; uv.y += DT_F * wv.y;
                uv.z += DT_F * wv.z; uv.w += DT_F * wv.w;
                sw[t] = wv; su[t] = uv;
            }
            __syncthreads();
        }
    } else if (eq == 1) {
        for (int step = 0; step < 3; ++step) {
            float4 du[8];
            #pragma unroll
            for (int i = 0; i < 8; ++i) {
                int t = tid + i * 256;
                float4 um2 = AT(su, t - 2), um1 = AT(su, t - 1);
                float4 up1 = AT(su, t + 1), up2 = AT(su, t + 2);
                float4 uc = su[t];
                #define KDV1(c) { \
                    float d1 = 0.5f * (up1.c - um1.c); \
                    float d3 = 0.5f * (up2.c - 2.f * up1.c + 2.f * um1.c - um2.c); \
                    du[i].c = DT_F * (-6.f * uc.c * d1 - d3); }
                KDV1(x) KDV1(y) KDV1(z) KDV1(w)
                #undef KDV1
            }
            __syncthreads();
            #pragma unroll
            for (int i = 0; i < 8; ++i) {
                int t = tid + i * 256;
                float4 uv = su[t];
                uv.x += du[i].x; uv.y += du[i].y; uv.z += du[i].z; uv.w += du[i].w;
                su[t] = uv;
            }
            __syncthreads();
        }
    } else {
        for (int step = 0; step < 3; ++step) {
            #pragma unroll
            for (int i = 0; i < 8; ++i) {
                int t = tid + i * 256;
                float4 v = su[t];
                sf[t].x = v.x - v.x * v.x + v.x * v.x * v.x;
                sf[t].y = v.y - v.y * v.y + v.y * v.y * v.y;
                sf[t].z = v.z - v.z * v.z + v.z * v.z * v.z;
                sf[t].w = v.w - v.w * v.w + v.w * v.w * v.w;
            }
            __syncthreads();
            float4 dw[8];
            #pragma unroll
            for (int i = 0; i < 8; ++i) {
                int t = tid + i * 256;
                float4 fm = AT(sf, t - 1), fp = AT(sf, t + 1), fc = sf[t];
                float4 um2 = AT(su, t - 2), um1 = AT(su, t - 1);
                float4 up1 = AT(su, t + 1), up2 = AT(su, t + 2);
                float4 uc = su[t];
                #define HJ1(c) { \
                    float d2f = fm.c - 2.f * fc.c + fp.c; \
                    float d4  = um2.c - 4.f * um1.c + 6.f * uc.c - 4.f * up1.c + up2.c; \
                    dw[i].c = DT_F * (d2f - HJ_HF * d4); }
                HJ1(x) HJ1(y) HJ1(z) HJ1(w)
                #undef HJ1
            }
            __syncthreads();
            #pragma unroll
            for (int i = 0; i < 8; ++i) {
                int t = tid + i * 256;
                float4 wv = sw[t], uv = su[t];
                wv.x += dw[i].x; wv.y += dw[i].y; wv.z += dw[i].z; wv.w += dw[i].w;
                uv.x += DT_F * wv.x; uv.y += DT_F * wv.y;
                uv.z += DT_F * wv.z; uv.w += DT_F * wv.w;
                sw[t] = wv; su[t] = uv;
            }
            __syncthreads();
        }
    }
    #undef AT

    for (int t = tid; t < SEQ; t += 256) {
        float4 v = su[t];
        uint32_t lo0, lo1;
        uint32_t hi0 = packsplit(v.x, v.y, lo0);
        uint32_t hi1 = packsplit(v.z, v.w, lo1);
        size_t o = base + (size_t)t * DIM;
        *reinterpret_cast<uint2*>(uh + o) = make_uint2(hi0, hi1);
        *reinterpret_cast<uint2*>(ul + o) = make_uint2(lo0, lo1);
    }
}

// ---------------------------------------------------------------------------
// Launch
// ---------------------------------------------------------------------------
extern "C" void kernel_launch(void* const* d_in, const int* in_sizes, int n_in,
                              void* d_out, int out_size)
{
    const float* x      = (const float*)d_in[0];
    const float* in_w   = (const float*)d_in[1];
    const float* in_b   = (const float*)d_in[2];
    const float* qkv_w[3] = {(const float*)d_in[3],  (const float*)d_in[7],  (const float*)d_in[11]};
    const float* qkv_b[3] = {(const float*)d_in[4],  (const float*)d_in[8],  (const float*)d_in[12]};
    const float* ow[3]    = {(const float*)d_in[5],  (const float*)d_in[9],  (const float*)d_in[13]};
    const float* ob[3]    = {(const float*)d_in[6],  (const float*)d_in[10], (const float*)d_in[14]};
    const float* out_w  = (const float*)d_in[15];
    const float* out_b  = (const float*)d_in[16];
    float* out = (float*)d_out;

    __nv_bfloat16 *xh, *xl, *hh, *hl, *qh, *ql, *ah, *al, *uh, *ul, *whi, *wlo;
    float* u;
    cudaGetSymbolAddress((void**)&xh, g_xh);  cudaGetSymbolAddress((void**)&xl, g_xl);
    cudaGetSymbolAddress((void**)&hh, g_hh);  cudaGetSymbolAddress((void**)&hl, g_hl);
    cudaGetSymbolAddress((void**)&qh, g_qh);  cudaGetSymbolAddress((void**)&ql, g_ql);
    cudaGetSymbolAddress((void**)&ah, g_ah);  cudaGetSymbolAddress((void**)&al, g_al);
    cudaGetSymbolAddress((void**)&uh, g_uh);  cudaGetSymbolAddress((void**)&ul, g_ul);
    cudaGetSymbolAddress((void**)&whi, g_whi); cudaGetSymbolAddress((void**)&wlo, g_wlo);
    cudaGetSymbolAddress((void**)&u, g_u);

    cudaFuncSetAttribute(attn_tc_kernel,
                         cudaFuncAttributeMaxDynamicSharedMemorySize, ATT_SMEM);
    cudaFuncSetAttribute(gemm_pp_kernel<true>,
                         cudaFuncAttributeMaxDynamicSharedMemorySize, GEMM_SMEM);
    cudaFuncSetAttribute(gemm_pp_kernel<false>,
                         cudaFuncAttributeMaxDynamicSharedMemorySize, GEMM_SMEM);
    cudaFuncSetAttribute(pde_all_kernel,
                         cudaFuncAttributeMaxDynamicSharedMemorySize, PDE_SMEM);

    // ---- weight prep ----
    WJobs jobs;
    jobs.W[0] = in_w;  jobs.hi[0] = whi + WT_IN;  jobs.lo[0] = wlo + WT_IN;
    jobs.K[0] = 768;   jobs.N[0] = 768;
    for (int g = 0; g < 3; ++g) {
        jobs.W[1 + g]  = qkv_w[g];
        jobs.hi[1 + g] = whi + WT_QKV0 + g * 768 * 256;
        jobs.lo[1 + g] = wlo + WT_QKV0 + g * 768 * 256;
        jobs.K[1 + g]  = 256; jobs.N[1 + g] = 768;
        jobs.W[4 + g]  = ow[g];
        jobs.hi[4 + g] = whi + WT_OW0 + g * 256 * 256;
        jobs.lo[4 + g] = wlo + WT_OW0 + g * 256 * 256;
        jobs.K[4 + g]  = 256; jobs.N[4 + g] = 256;
    }
    jobs.W[7] = out_w; jobs.hi[7] = whi + WT_OUT; jobs.lo[7] = wlo + WT_OUT;
    jobs.K[7] = 768;   jobs.N[7] = 768;
    wsplit_all_kernel<<<dim3(24, 24, 8), dim3(32, 8)>>>(jobs);

    asplit_kernel<<<MD / 1024, 256>>>(x, xh, xl, MD);

    // 1) h = x @ in_w + in_b
    {
        GemmArgs a{};
        a.Ah[0] = xh; a.Al[0] = xl; a.lda = DIM; a.K = 768;
        a.Bh[0] = whi + WT_IN; a.Bl[0] = wlo + WT_IN; a.bias[0] = in_b;
        a.Ch[0] = hh; a.Cl[0] = hl; a.ldc = DIM; a.qcols = 0;
        gemm_pp_kernel<true><<<dim3(6, 64, 1), 256, GEMM_SMEM>>>(a);
    }

    // 2) qkv (fused over groups; Q columns pre-scaled by 0.125*log2e)
    {
        GemmArgs a{};
        for (int g = 0; g < 3; ++g) {
            a.Ah[g] = hh + g * GDIM; a.Al[g] = hl + g * GDIM;
            a.Bh[g] = whi + WT_QKV0 + g * 768 * 256;
            a.Bl[g] = wlo + WT_QKV0 + g * 768 * 256;
            a.bias[g] = qkv_b[g];
            a.Ch[g] = qh + (size_t)g * MD; a.Cl[g] = ql + (size_t)g * MD;
        }
        a.lda = DIM; a.K = 256; a.ldc = DIM; a.qcols = 256;
        gemm_pp_kernel<true><<<dim3(6, 64, 3), 256, GEMM_SMEM>>>(a);
    }

    // 3) attention
    attn_tc_kernel<<<dim3(SEQ / 128, BATCH * 4, 3), 256, ATT_SMEM>>>(qh, ql, ah, al);

    // 4) out projection (fused, fp32 output into u)
    {
        GemmArgs a{};
        for (int g = 0; g < 3; ++g) {
            a.Ah[g] = ah + g * GDIM; a.Al[g] = al + g * GDIM;
            a.Bh[g] = whi + WT_OW0 + g * 256 * 256;
            a.Bl[g] = wlo + WT_OW0 + g * 256 * 256;
            a.bias[g] = ob[g];
            a.Cf[g] = u + g * GDIM;
        }
        a.lda = DIM; a.K = 256; a.ldc = DIM; a.qcols = 0;
        gemm_pp_kernel<false><<<dim3(2, 64, 3), 256, GEMM_SMEM>>>(a);
    }

    // 5) PDE (one launch, float4 channel tiles, split-plane output)
    pde_all_kernel<<<dim3(BATCH * 64, 3), 256, PDE_SMEM>>>(u, uh, ul);

    // 6) out = u @ out_w + out_b
    {
        GemmArgs a{};
        a.Ah[0] = uh; a.Al[0] = ul; a.lda = DIM; a.K = 768;
        a.Bh[0] = whi + WT_OUT; a.Bl[0] = wlo + WT_OUT; a.bias[0] = out_b;
        a.Cf[0] = out; a.ldc = DIM; a.qcols = 0;
        gemm_pp_kernel<false><<<dim3(6, 64, 1), 256, GEMM_SMEM>>>(a);
    }
}

// round 17
// speedup vs baseline: 1.0543x; 1.0543x over previous
#include <cuda_runtime.h>
#include <cuda_bf16.h>
#include <math.h>
#include <stdint.h>

// ---------------------------------------------------------------------------
// Problem constants
// ---------------------------------------------------------------------------
constexpr int BATCH = 4;
constexpr int SEQ   = 2048;
constexpr int DIM   = 768;
constexpr int GDIM  = 256;
constexpr int HDIM  = 64;
constexpr int MROWS = BATCH * SEQ;   // 8192
constexpr float DT_F  = 0.05f;
constexpr float HJ_HF = 0.05f;
constexpr int MD = MROWS * DIM;

// ---------------------------------------------------------------------------
// Device scratch (no cudaMalloc allowed)
// ---------------------------------------------------------------------------
__device__ __nv_bfloat16 g_xh[MD],  g_xl[MD];
__device__ __nv_bfloat16 g_hh[MD],  g_hl[MD];
__device__ __nv_bfloat16 g_qh[3 * MD], g_ql[3 * MD];
__device__ __nv_bfloat16 g_ah[MD],  g_al[MD];
__device__ __nv_bfloat16 g_uh[MD],  g_ul[MD];
__device__ float g_u[MD];

constexpr int WT_IN   = 0;
constexpr int WT_QKV0 = WT_IN   + 768 * 768;
constexpr int WT_OW0  = WT_QKV0 + 3 * 768 * 256;
constexpr int WT_OUT  = WT_OW0  + 3 * 256 * 256;
constexpr int WT_TOTAL = WT_OUT + 768 * 768;
__device__ __nv_bfloat16 g_whi[WT_TOTAL];
__device__ __nv_bfloat16 g_wlo[WT_TOTAL];

// ---------------------------------------------------------------------------
// Helpers
// ---------------------------------------------------------------------------
__device__ __forceinline__ uint32_t smem_u32(const void* p) {
    uint32_t a;
    asm("{ .reg .u64 t; cvta.to.shared.u64 t, %1; cvt.u32.u64 %0, t; }"
        : "=r"(a) : "l"(p));
    return a;
}
__device__ __forceinline__ void split_bf(float v, __nv_bfloat16& h, __nv_bfloat16& l) {
    h = __float2bfloat16_rn(v);
    l = __float2bfloat16_rn(v - __bfloat162float(h));
}
// Fast truncation-based split: hi pair = PRMT of the two fp32 upper halves
// (exact bf16 truncation); lo pair = rn(residual) packed with one bf16x2 cvt.
__device__ __forceinline__ uint32_t packsplit(float a, float b, uint32_t& lo) {
    uint32_t ua = __float_as_uint(a), ub = __float_as_uint(b);
    uint32_t hi;
    asm("prmt.b32 %0, %1, %2, 0x7632;" : "=r"(hi) : "r"(ua), "r"(ub));
    float ra = a - __uint_as_float(ua & 0xFFFF0000u);
    float rb = b - __uint_as_float(ub & 0xFFFF0000u);
    asm("cvt.rn.bf16x2.f32 %0, %1, %2;" : "=r"(lo) : "f"(rb), "f"(ra));
    return hi;
}
__device__ __forceinline__ void ldsm_x4(uint32_t* r, uint32_t a) {
    asm volatile("ldmatrix.sync.aligned.m8n8.x4.shared.b16 {%0,%1,%2,%3}, [%4];"
        : "=r"(r[0]), "=r"(r[1]), "=r"(r[2]), "=r"(r[3]) : "r"(a));
}
__device__ __forceinline__ void ldsm_x4t(uint32_t* r, uint32_t a) {
    asm volatile("ldmatrix.sync.aligned.m8n8.x4.trans.shared.b16 {%0,%1,%2,%3}, [%4];"
        : "=r"(r[0]), "=r"(r[1]), "=r"(r[2]), "=r"(r[3]) : "r"(a));
}
__device__ __forceinline__ void mma_bf16(float* c, const uint32_t* a, const uint32_t* b) {
    asm volatile("mma.sync.aligned.m16n8k16.row.col.f32.bf16.bf16.f32 "
        "{%0,%1,%2,%3}, {%4,%5,%6,%7}, {%8,%9}, {%0,%1,%2,%3};"
        : "+f"(c[0]), "+f"(c[1]), "+f"(c[2]), "+f"(c[3])
        : "r"(a[0]), "r"(a[1]), "r"(a[2]), "r"(a[3]), "r"(b[0]), "r"(b[1]));
}
// .ca restored: R16 proved L1-bypass (.cg) is a net loss on this workload.
__device__ __forceinline__ void cp_async16(uint32_t d, const void* s) {
    asm volatile("cp.async.ca.shared.global [%0], [%1], 16;" :: "r"(d), "l"(s) : "memory");
}
__device__ __forceinline__ void cp_commit() {
    asm volatile("cp.async.commit_group;" ::: "memory");
}
__device__ __forceinline__ void cp_wait0() {
    asm volatile("cp.async.wait_group 0;" ::: "memory");
}
__device__ __forceinline__ void cp_wait1() {
    asm volatile("cp.async.wait_group 1;" ::: "memory");
}

// ---------------------------------------------------------------------------
// Prep: all 8 weight splits + the activation split of x in ONE launch.
// grid (24, 24, 9); z<8 = weight jobs, z==8 = x split (grid-stride).
// ---------------------------------------------------------------------------
struct WJobs {
    const float* W[8];
    __nv_bfloat16* hi[8];
    __nv_bfloat16* lo[8];
    int K[8];
    int N[8];
    const float* Ax;
    __nv_bfloat16* Axh;
    __nv_bfloat16* Axl;
    int An;
};

__global__ void prep_all_kernel(WJobs jobs)
{
    const int id = blockIdx.z;
    const int tid = threadIdx.y * 32 + threadIdx.x;

    if (id == 8) {
        // activation split of x, grid-strided over (24*24) blocks
        const int nb = gridDim.x * gridDim.y;               // 576
        const int bid = blockIdx.y * gridDim.x + blockIdx.x;
        const float* A = jobs.Ax;
        __nv_bfloat16* hi = jobs.Axh;
        __nv_bfloat16* lo = jobs.Axl;
        for (int i = (bid * 256 + tid) * 4; i < jobs.An; i += nb * 256 * 4) {
            float4 v = *reinterpret_cast<const float4*>(A + i);
            uint32_t lo0, lo1;
            uint32_t hi0 = packsplit(v.x, v.y, lo0);
            uint32_t hi1 = packsplit(v.z, v.w, lo1);
            *reinterpret_cast<uint2*>(hi + i) = make_uint2(hi0, hi1);
            *reinterpret_cast<uint2*>(lo + i) = make_uint2(lo0, lo1);
        }
        return;
    }

    const int K = jobs.K[id], N = jobs.N[id];
    const int kb = blockIdx.y * 32;
    const int nb = blockIdx.x * 32;
    if (kb >= K || nb >= N) return;

    const float* W = jobs.W[id];
    __nv_bfloat16* Whi = jobs.hi[id];
    __nv_bfloat16* Wlo = jobs.lo[id];

    __shared__ float tile[32][33];
    const int tx = threadIdx.x;
    for (int i = threadIdx.y; i < 32; i += 8)
        tile[i][tx] = W[(size_t)(kb + i) * N + nb + tx];
    __syncthreads();
    for (int i = threadIdx.y; i < 32; i += 8) {
        float v = tile[tx][i];
        __nv_bfloat16 h, l;
        split_bf(v, h, l);
        size_t o = (size_t)(nb + i) * K + kb + tx;
        Whi[o] = h;
        Wlo[o] = l;
    }
}

// ---------------------------------------------------------------------------
// bf16x3 HMMA GEMM (R14 config: BM=128, BN=128, BK=32, 256 threads, 2 CTAs/SM).
// qcols: output columns < qcols scaled by 0.125*log2(e) (Q pre-scale + exp2).
// ---------------------------------------------------------------------------
constexpr int GPLANE = 128 * 80;              // 10240 B per plane
constexpr int GSTAGE = 4 * GPLANE;            // Ah|Al|Bh|Bl = 40960 B
constexpr int GEMM_SMEM = 2 * GSTAGE;         // 81920 B -> 2 CTAs/SM
constexpr float QSCALE = 0.125f * 1.4426950408889634f;

struct GemmArgs {
    const __nv_bfloat16* Ah[3];
    const __nv_bfloat16* Al[3];
    int lda, K;
    const __nv_bfloat16* Bh[3];
    const __nv_bfloat16* Bl[3];
    const float* bias[3];
    float* Cf[3];
    __nv_bfloat16* Ch[3];
    __nv_bfloat16* Cl[3];
    int ldc;
    int qcols;
};

template<bool OUT_SPLIT>
__global__ __launch_bounds__(256)
void gemm_pp_kernel(GemmArgs p)
{
    extern __shared__ char smc[];
    const uint32_t sbase = smem_u32(smc);

    const int tid  = threadIdx.x;
    const int lane = tid & 31;
    const int wid  = tid >> 5;
    const int wm   = wid & 1;
    const int wn   = wid >> 1;
    const int m0 = blockIdx.y * 128;
    const int n0 = blockIdx.x * 128;
    const int z  = blockIdx.z;
    const int KT = p.K / 32;

    const __nv_bfloat16* Ah = p.Ah[z];
    const __nv_bfloat16* Al = p.Al[z];
    const __nv_bfloat16* Bh = p.Bh[z];
    const __nv_bfloat16* Bl = p.Bl[z];

    float acc[4][4][4];
    #pragma unroll
    for (int i = 0; i < 4; ++i)
        #pragma unroll
        for (int j = 0; j < 4; ++j)
            #pragma unroll
            for (int k = 0; k < 4; ++k) acc[i][j][k] = 0.f;

    auto stage = [&](int kt, int s) {
        #pragma unroll
        for (int j = 0; j < 8; ++j) {
            int cid = tid + 256 * j;
            int plane = cid >> 9;
            int idx = cid & 511;
            int row = idx >> 2;
            int ch  = idx & 3;
            const __nv_bfloat16* src;
            if      (plane == 0) src = Ah + (size_t)(m0 + row) * p.lda + kt * 32 + ch * 8;
            else if (plane == 1) src = Al + (size_t)(m0 + row) * p.lda + kt * 32 + ch * 8;
            else if (plane == 2) src = Bh + (size_t)(n0 + row) * p.K + kt * 32 + ch * 8;
            else                 src = Bl + (size_t)(n0 + row) * p.K + kt * 32 + ch * 8;
            cp_async16(sbase + s * GSTAGE + plane * GPLANE + row * 80 + ch * 16, src);
        }
    };

    const int lr16 = lane & 15;
    const int lk8  = (lane >> 4) * 8;
    const int br  = (lane & 7) + ((lane >> 4) << 3);
    const int bkl = ((lane >> 3) & 1) * 8;

    auto compute = [&](int s) {
        const uint32_t st = sbase + s * GSTAGE;
        #pragma unroll
        for (int ks = 0; ks < 32; ks += 16) {
            uint32_t bh[4][2], bl[4][2];
            #pragma unroll
            for (int pair = 0; pair < 2; ++pair) {
                uint32_t rb = st + 2 * GPLANE
                            + ((wn * 32 + pair * 16 + br) * 80) + (ks + bkl) * 2;
                uint32_t t[4], tl[4];
                ldsm_x4(t, rb);
                ldsm_x4(tl, rb + GPLANE);
                bh[pair * 2][0] = t[0];  bh[pair * 2][1] = t[1];
                bh[pair * 2 + 1][0] = t[2]; bh[pair * 2 + 1][1] = t[3];
                bl[pair * 2][0] = tl[0]; bl[pair * 2][1] = tl[1];
                bl[pair * 2 + 1][0] = tl[2]; bl[pair * 2 + 1][1] = tl[3];
            }
            #pragma unroll
            for (int mt = 0; mt < 4; ++mt) {
                uint32_t ra = st + (wm * 64 + mt * 16 + lr16) * 80 + (ks + lk8) * 2;
                uint32_t ah[4], al[4];
                ldsm_x4(ah, ra);
                ldsm_x4(al, ra + GPLANE);
                #pragma unroll
                for (int nt = 0; nt < 4; ++nt) {
                    mma_bf16(acc[mt][nt], ah, bh[nt]);
                    mma_bf16(acc[mt][nt], ah, bl[nt]);
                    mma_bf16(acc[mt][nt], al, bh[nt]);
                }
            }
        }
    };

    stage(0, 0);
    cp_commit();
    for (int kt = 0; kt < KT; ++kt) {
        const int s = kt & 1;
        const bool more = kt + 1 < KT;
        if (more) {
            stage(kt + 1, s ^ 1);
            cp_commit();
            cp_wait1();
        } else {
            cp_wait0();
        }
        __syncthreads();
        compute(s);
        __syncthreads();
    }

    #pragma unroll
    for (int mt = 0; mt < 4; ++mt) {
        int r0 = m0 + wm * 64 + mt * 16 + (lane >> 2);
        #pragma unroll
        for (int nt = 0; nt < 4; ++nt) {
            int col = n0 + wn * 32 + nt * 8 + (lane & 3) * 2;
            float qs = (col < p.qcols) ? QSCALE : 1.0f;
            float2 bv = *reinterpret_cast<const float2*>(p.bias[z] + col);
            float c00 = (acc[mt][nt][0] + bv.x) * qs, c01 = (acc[mt][nt][1] + bv.y) * qs;
            float c10 = (acc[mt][nt][2] + bv.x) * qs, c11 = (acc[mt][nt][3] + bv.y) * qs;
            if (OUT_SPLIT) {
                uint32_t lo0, lo1;
                uint32_t hi0 = packsplit(c00, c01, lo0);
                uint32_t hi1 = packsplit(c10, c11, lo1);
                __nv_bfloat16* Ch = p.Ch[z];
                __nv_bfloat16* Cl = p.Cl[z];
                *reinterpret_cast<uint32_t*>(Ch + (size_t)r0 * p.ldc + col) = hi0;
                *reinterpret_cast<uint32_t*>(Cl + (size_t)r0 * p.ldc + col) = lo0;
                *reinterpret_cast<uint32_t*>(Ch + (size_t)(r0 + 8) * p.ldc + col) = hi1;
                *reinterpret_cast<uint32_t*>(Cl + (size_t)(r0 + 8) * p.ldc + col) = lo1;
            } else {
                float* Cf = p.Cf[z];
                *reinterpret_cast<float2*>(Cf + (size_t)r0 * p.ldc + col) =
                    make_float2(c00, c01);
                *reinterpret_cast<float2*>(Cf + (size_t)(r0 + 8) * p.ldc + col) =
                    make_float2(c10, c11);
            }
        }
    }
}

// ---------------------------------------------------------------------------
// Tensor-core flash attention: Q tile 128, KV tile 64, three-stage pipeline
// (Q SMEM region recycled as the 3rd KV buffer once Q-fragments are in regs).
// jt_max = 2*qt+1. Commit only real transfers; wait1 while a successor
// data-group is in flight (jt < jt_max), else wait0. exp2-domain softmax.
// ---------------------------------------------------------------------------
constexpr int AP = 72;
constexpr int AQL = 18432;
constexpr int AKV0 = 36864, AKVS = 36864;
constexpr int ATT_SMEM = AKV0 + 2 * AKVS;   // 110592 -> 2 CTAs/SM

__global__ __launch_bounds__(256)
void attn_tc_kernel(const __nv_bfloat16* __restrict__ qkvh,
                    const __nv_bfloat16* __restrict__ qkvl,
                    __nv_bfloat16* __restrict__ attnh,
                    __nv_bfloat16* __restrict__ attnl)
{
    extern __shared__ char smb[];
    const uint32_t S = smem_u32(smb);

    const int tid  = threadIdx.x;
    const int lane = tid & 31;
    const int w    = tid >> 5;
    const int qt = gridDim.x - 1 - blockIdx.x;   // heavy blocks first
    const int bh_ = blockIdx.y;
    const int g  = blockIdx.z;
    const int b  = bh_ >> 2;
    const int h  = bh_ & 3;
    const int q0 = qt * 128;
    const int jt_max = 2 * qt + 1;

    const size_t gb = (size_t)g * MROWS * DIM + (size_t)b * SEQ * DIM;
    const __nv_bfloat16* ph = qkvh + gb;
    const __nv_bfloat16* pl = qkvl + gb;
    const int qo = h * HDIM;
    const int ko = GDIM + h * HDIM;
    const int vo = 2 * GDIM + h * HDIM;

    auto buf_base = [&](int jt) -> uint32_t {
        int bi = jt % 3;
        return (bi == 2) ? S : (S + AKV0 + bi * AKVS);
    };

    auto stage_kv = [&](int jt) {
        const int j0 = jt * 64;
        const uint32_t B = buf_base(jt);
        #pragma unroll
        for (int j = 0; j < 8; ++j) {
            int cid = tid + 256 * j;
            int plane = cid >> 9;          // 0 Kh, 1 Kl, 2 Vh, 3 Vl
            int idx = cid & 511;
            int row = idx >> 3;
            int ch  = idx & 7;
            const __nv_bfloat16* bp = (plane & 1) ? pl : ph;
            int co = (plane >> 1) ? vo : ko;
            cp_async16(B + plane * 9216 + (row * AP + ch * 8) * 2,
                       bp + (size_t)(j0 + row) * DIM + co + ch * 8);
        }
    };

    // Q stage into buffer-2 area (consumed into registers at jt=0)
    #pragma unroll
    for (int j = 0; j < 8; ++j) {
        int cid = tid + 256 * j;
        int plane = cid >> 10;
        int idx = cid & 1023;
        int row = idx >> 3;
        int ch  = idx & 7;
        const __nv_bfloat16* bp = plane ? pl : ph;
        cp_async16(S + plane * AQL + (row * AP + ch * 8) * 2,
                   bp + (size_t)(q0 + row) * DIM + qo + ch * 8);
    }
    stage_kv(0);
    cp_commit();                                   // group: Q + KV0
    if (jt_max >= 1) { stage_kv(1); cp_commit(); } // group: KV1

    uint32_t aqh[4][4], aql[4][4];

    float m_[2] = {-1e30f, -1e30f};
    float l_[2] = {0.f, 0.f};
    float oacc[8][4];
    #pragma unroll
    for (int j = 0; j < 8; ++j)
        #pragma unroll
        for (int r = 0; r < 4; ++r) oacc[j][r] = 0.f;

    const int lr16 = lane & 15;
    const int lk8  = (lane >> 4) * 8;
    const int br   = (lane & 7) + ((lane >> 4) << 3);
    const int bkl  = ((lane >> 3) & 1) * 8;

    for (int jt = 0; jt <= jt_max; ++jt) {
        if (jt < jt_max) cp_wait1(); else cp_wait0();
        __syncthreads();

        if (jt == 0) {
            const int ar = w * 16 + lr16;
            #pragma unroll
            for (int ks = 0; ks < 4; ++ks) {
                uint32_t a = S + (ar * AP + ks * 16 + lk8) * 2;
                ldsm_x4(aqh[ks], a);
                ldsm_x4(aql[ks], a + AQL);
            }
            __syncthreads();
        }

        if (jt + 2 <= jt_max) { stage_kv(jt + 2); cp_commit(); }

        const int j0 = jt * 64;
        if (j0 <= q0 + w * 16 + 15) {
            const uint32_t KB = buf_base(jt);

            float sacc[8][4];
            #pragma unroll
            for (int j = 0; j < 8; ++j)
                #pragma unroll
                for (int r = 0; r < 4; ++r) sacc[j][r] = 0.f;

            #pragma unroll
            for (int ks = 0; ks < 4; ++ks) {
                uint32_t bhf[4][4], blf[4][4];
                #pragma unroll
                for (int np = 0; np < 4; ++np) {
                    uint32_t a = KB + ((np * 16 + br) * AP + ks * 16 + bkl) * 2;
                    ldsm_x4(bhf[np], a);
                    ldsm_x4(blf[np], a + 9216);
                }
                #pragma unroll
                for (int np = 0; np < 4; ++np) {
                    mma_bf16(sacc[2 * np],     aqh[ks], &bhf[np][0]);
                    mma_bf16(sacc[2 * np + 1], aqh[ks], &bhf[np][2]);
                }
                #pragma unroll
                for (int np = 0; np < 4; ++np) {
                    mma_bf16(sacc[2 * np],     aqh[ks], &blf[np][0]);
                    mma_bf16(sacc[2 * np + 1], aqh[ks], &blf[np][2]);
                }
                #pragma unroll
                for (int np = 0; np < 4; ++np) {
                    mma_bf16(sacc[2 * np],     aql[ks], &bhf[np][0]);
                    mma_bf16(sacc[2 * np + 1], aql[ks], &bhf[np][2]);
                }
            }

            const int rbase = q0 + w * 16 + (lane >> 2);
            const int cbase = (lane & 3) * 2;
            if (j0 + 63 > q0 + w * 16) {
                #pragma unroll
                for (int j = 0; j < 8; ++j)
                    #pragma unroll
                    for (int rw = 0; rw < 2; ++rw)
                        #pragma unroll
                        for (int c = 0; c < 2; ++c)
                            if (j0 + j * 8 + cbase + c > rbase + rw * 8)
                                sacc[j][rw * 2 + c] = -1e30f;
            }

            #pragma unroll
            for (int rw = 0; rw < 2; ++rw) {
                float rm = -1e30f;
                #pragma unroll
                for (int j = 0; j < 8; ++j) {
                    rm = fmaxf(rm, sacc[j][rw * 2]);
                    rm = fmaxf(rm, sacc[j][rw * 2 + 1]);
                }
                rm = fmaxf(rm, __shfl_xor_sync(0xffffffffu, rm, 1));
                rm = fmaxf(rm, __shfl_xor_sync(0xffffffffu, rm, 2));
                const float mnew  = fmaxf(m_[rw], rm);
                const float alpha = exp2f(m_[rw] - mnew);
                m_[rw] = mnew;
                float rs = 0.f;
                #pragma unroll
                for (int j = 0; j < 8; ++j) {
                    float p0 = exp2f(sacc[j][rw * 2]     - mnew);
                    float p1 = exp2f(sacc[j][rw * 2 + 1] - mnew);
                    sacc[j][rw * 2]     = p0;
                    sacc[j][rw * 2 + 1] = p1;
                    rs += p0 + p1;
                }
                rs += __shfl_xor_sync(0xffffffffu, rs, 1);
                rs += __shfl_xor_sync(0xffffffffu, rs, 2);
                l_[rw] = l_[rw] * alpha + rs;
                #pragma unroll
                for (int j = 0; j < 8; ++j) {
                    oacc[j][rw * 2]     *= alpha;
                    oacc[j][rw * 2 + 1] *= alpha;
                }
            }

            uint32_t ph4[4][4], pl4[4][4];
            #pragma unroll
            for (int u = 0; u < 4; ++u) {
                ph4[u][0] = packsplit(sacc[2 * u][0],     sacc[2 * u][1],     pl4[u][0]);
                ph4[u][1] = packsplit(sacc[2 * u][2],     sacc[2 * u][3],     pl4[u][1]);
                ph4[u][2] = packsplit(sacc[2 * u + 1][0], sacc[2 * u + 1][1], pl4[u][2]);
                ph4[u][3] = packsplit(sacc[2 * u + 1][2], sacc[2 * u + 1][3], pl4[u][3]);
            }

            {
                const int vk = ((lane >> 3) & 1) * 8 + (lane & 7);
                const int vn = (lane >> 4) * 8;
                const uint32_t VB = KB + 18432;
                #pragma unroll
                for (int u = 0; u < 4; ++u) {
                    uint32_t bvh[4][4], bvl[4][4];
                    #pragma unroll
                    for (int np = 0; np < 4; ++np) {
                        uint32_t a = VB + ((u * 16 + vk) * AP + np * 16 + vn) * 2;
                        ldsm_x4t(bvh[np], a);
                        ldsm_x4t(bvl[np], a + 9216);
                    }
                    #pragma unroll
                    for (int np = 0; np < 4; ++np) {
                        mma_bf16(oacc[2 * np],     ph4[u], &bvh[np][0]);
                        mma_bf16(oacc[2 * np + 1], ph4[u], &bvh[np][2]);
                    }
                    #pragma unroll
                    for (int np = 0; np < 4; ++np) {
                        mma_bf16(oacc[2 * np],     ph4[u], &bvl[np][0]);
                        mma_bf16(oacc[2 * np + 1], ph4[u], &bvl[np][2]);
                    }
                    #pragma unroll
                    for (int np = 0; np < 4; ++np) {
                        mma_bf16(oacc[2 * np],     pl4[u], &bvh[np][0]);
                        mma_bf16(oacc[2 * np + 1], pl4[u], &bvh[np][2]);
                    }
                }
            }
        }
    }

    #pragma unroll
    for (int rw = 0; rw < 2; ++rw) {
        const float inv = 1.0f / l_[rw];
        const size_t row = (size_t)b * SEQ + q0 + w * 16 + (lane >> 2) + rw * 8;
        const size_t off = row * DIM + g * GDIM + h * HDIM + (lane & 3) * 2;
        #pragma unroll
        for (int j = 0; j < 8; ++j) {
            uint32_t lo;
            uint32_t hi = packsplit(oacc[j][rw * 2] * inv,
                                    oacc[j][rw * 2 + 1] * inv, lo);
            *reinterpret_cast<uint32_t*>(attnh + off + j * 8) = hi;
            *reinterpret_cast<uint32_t*>(attnl + off + j * 8) = lo;
        }
    }
}

// ---------------------------------------------------------------------------
// Fused PDE kernel, 4 channels per block (float4 lanes), blockIdx.y = equation.
// sf removed: HJ recomputes f(u)=u-u^2+u^3 inline at t-1/t/t+1 (exact same
// fp32 ops) -> SMEM 65536 B -> 3 CTAs/SM, and one less sync per HJ step.
// ---------------------------------------------------------------------------
constexpr int PDE_SMEM = 2 * SEQ * 16;

__global__ void pde_all_kernel(const float* __restrict__ u,
                               __nv_bfloat16* __restrict__ uh,
                               __nv_bfloat16* __restrict__ ul)
{
    const int eq = blockIdx.y;
    const int b  = blockIdx.x >> 6;
    const int c4 = blockIdx.x & 63;
    const size_t base = (size_t)b * SEQ * DIM + eq * GDIM + c4 * 4;

    extern __shared__ float4 sp[];
    float4* su = sp;
    float4* sw = sp + SEQ;
    const int tid = threadIdx.x;
    const float4 z4 = make_float4(0.f, 0.f, 0.f, 0.f);

    for (int t = tid; t < SEQ; t += 256) {
        su[t] = *reinterpret_cast<const float4*>(u + base + (size_t)t * DIM);
        sw[t] = z4;
    }
    __syncthreads();

    #define AT(arr, t) ((t) >= 0 && (t) < SEQ ? arr[t] : z4)
    #define FPOLY(v) ((v) - (v) * (v) + (v) * (v) * (v))

    if (eq == 0) {
        for (int step = 0; step < 3; ++step) {
            float4 dw[8];
            #pragma unroll
            for (int i = 0; i < 8; ++i) {
                int t = tid + i * 256;
                float4 um = AT(su, t - 1), up = AT(su, t + 1), uc = su[t];
                dw[i].x = DT_F * ((um.x - 2.f * uc.x + up.x) - sinf(uc.x));
                dw[i].y = DT_F * ((um.y - 2.f * uc.y + up.y) - sinf(uc.y));
                dw[i].z = DT_F * ((um.z - 2.f * uc.z + up.z) - sinf(uc.z));
                dw[i].w = DT_F * ((um.w - 2.f * uc.w + up.w) - sinf(uc.w));
            }
            __syncthreads();
            #pragma unroll
            for (int i = 0; i < 8; ++i) {
                int t = tid + i * 256;
                float4 wv = sw[t], uv = su[t];
                wv.x += dw[i].x; wv.y += dw[i].y; wv.z += dw[i].z; wv.w += dw[i].w;
                uv.x += DT_F * wv.x; uv.y += DT_F * wv.y;
                uv.z += DT_F * wv.z; uv.w += DT_F * wv.w;
                sw[t] = wv; su[t] = uv;
            }
            __syncthreads();
        }
    } else if (eq == 1) {
        for (int step = 0; step < 3; ++step) {
            float4 du[8];
            #pragma unroll
            for (int i = 0; i < 8; ++i) {
                int t = tid + i * 256;
                float4 um2 = AT(su, t - 2), um1 = AT(su, t - 1);
                float4 up1 = AT(su, t + 1), up2 = AT(su, t + 2);
                float4 uc = su[t];
                #define KDV1(c) { \
                    float d1 = 0.5f * (up1.c - um1.c); \
                    float d3 = 0.5f * (up2.c - 2.f * up1.c + 2.f * um1.c - um2.c); \
                    du[i].c = DT_F * (-6.f * uc.c * d1 - d3); }
                KDV1(x) KDV1(y) KDV1(z) KDV1(w)
                #undef KDV1
            }
            __syncthreads();
            #pragma unroll
            for (int i = 0; i < 8; ++i) {
                int t = tid + i * 256;
                float4 uv = su[t];
                uv.x += du[i].x; uv.y += du[i].y; uv.z += du[i].z; uv.w += du[i].w;
                su[t] = uv;
            }
            __syncthreads();
        }
    } else {
        for (int step = 0; step < 3; ++step) {
            float4 dw[8];
            #pragma unroll
            for (int i = 0; i < 8; ++i) {
                int t = tid + i * 256;
                float4 um2 = AT(su, t - 2), um1 = AT(su, t - 1);
                float4 up1 = AT(su, t + 1), up2 = AT(su, t + 2);
                float4 uc = su[t];
                #define HJ1(c) { \
                    float fm = FPOLY(um1.c), fc = FPOLY(uc.c), fp = FPOLY(up1.c); \
                    float d2f = fm - 2.f * fc + fp; \
                    float d4  = um2.c - 4.f * um1.c + 6.f * uc.c - 4.f * up1.c + up2.c; \
                    dw[i].c = DT_F * (d2f - HJ_HF * d4); }
                HJ1(x) HJ1(y) HJ1(z) HJ1(w)
                #undef HJ1
            }
            __syncthreads();
            #pragma unroll
            for (int i = 0; i < 8; ++i) {
                int t = tid + i * 256;
                float4 wv = sw[t], uv = su[t];
                wv.x += dw[i].x; wv.y += dw[i].y; wv.z += dw[i].z; wv.w += dw[i].w;
                uv.x += DT_F * wv.x; uv.y += DT_F * wv.y;
                uv.z += DT_F * wv.z; uv.w += DT_F * wv.w;
                sw[t] = wv; su[t] = uv;
            }
            __syncthreads();
        }
    }
    #undef FPOLY
    #undef AT

    for (int t = tid; t < SEQ; t += 256) {
        float4 v = su[t];
        uint32_t lo0, lo1;
        uint32_t hi0 = packsplit(v.x, v.y, lo0);
        uint32_t hi1 = packsplit(v.z, v.w, lo1);
        size_t o = base + (size_t)t * DIM;
        *reinterpret_cast<uint2*>(uh + o) = make_uint2(hi0, hi1);
        *reinterpret_cast<uint2*>(ul + o) = make_uint2(lo0, lo1);
    }
}

// ---------------------------------------------------------------------------
// Launch
// ---------------------------------------------------------------------------
extern "C" void kernel_launch(void* const* d_in, const int* in_sizes, int n_in,
                              void* d_out, int out_size)
{
    const float* x      = (const float*)d_in[0];
    const float* in_w   = (const float*)d_in[1];
    const float* in_b   = (const float*)d_in[2];
    const float* qkv_w[3] = {(const float*)d_in[3],  (const float*)d_in[7],  (const float*)d_in[11]};
    const float* qkv_b[3] = {(const float*)d_in[4],  (const float*)d_in[8],  (const float*)d_in[12]};
    const float* ow[3]    = {(const float*)d_in[5],  (const float*)d_in[9],  (const float*)d_in[13]};
    const float* ob[3]    = {(const float*)d_in[6],  (const float*)d_in[10], (const float*)d_in[14]};
    const float* out_w  = (const float*)d_in[15];
    const float* out_b  = (const float*)d_in[16];
    float* out = (float*)d_out;

    __nv_bfloat16 *xh, *xl, *hh, *hl, *qh, *ql, *ah, *al, *uh, *ul, *whi, *wlo;
    float* u;
    cudaGetSymbolAddress((void**)&xh, g_xh);  cudaGetSymbolAddress((void**)&xl, g_xl);
    cudaGetSymbolAddress((void**)&hh, g_hh);  cudaGetSymbolAddress((void**)&hl, g_hl);
    cudaGetSymbolAddress((void**)&qh, g_qh);  cudaGetSymbolAddress((void**)&ql, g_ql);
    cudaGetSymbolAddress((void**)&ah, g_ah);  cudaGetSymbolAddress((void**)&al, g_al);
    cudaGetSymbolAddress((void**)&uh, g_uh);  cudaGetSymbolAddress((void**)&ul, g_ul);
    cudaGetSymbolAddress((void**)&whi, g_whi); cudaGetSymbolAddress((void**)&wlo, g_wlo);
    cudaGetSymbolAddress((void**)&u, g_u);

    cudaFuncSetAttribute(attn_tc_kernel,
                         cudaFuncAttributeMaxDynamicSharedMemorySize, ATT_SMEM);
    cudaFuncSetAttribute(gemm_pp_kernel<true>,
                         cudaFuncAttributeMaxDynamicSharedMemorySize, GEMM_SMEM);
    cudaFuncSetAttribute(gemm_pp_kernel<false>,
                         cudaFuncAttributeMaxDynamicSharedMemorySize, GEMM_SMEM);
    cudaFuncSetAttribute(pde_all_kernel,
                         cudaFuncAttributeMaxDynamicSharedMemorySize, PDE_SMEM);

    // ---- prep: weight splits + x split in one launch ----
    WJobs jobs;
    jobs.W[0] = in_w;  jobs.hi[0] = whi + WT_IN;  jobs.lo[0] = wlo + WT_IN;
    jobs.K[0] = 768;   jobs.N[0] = 768;
    for (int g = 0; g < 3; ++g) {
        jobs.W[1 + g]  = qkv_w[g];
        jobs.hi[1 + g] = whi + WT_QKV0 + g * 768 * 256;
        jobs.lo[1 + g] = wlo + WT_QKV0 + g * 768 * 256;
        jobs.K[1 + g]  = 256; jobs.N[1 + g] = 768;
        jobs.W[4 + g]  = ow[g];
        jobs.hi[4 + g] = whi + WT_OW0 + g * 256 * 256;
        jobs.lo[4 + g] = wlo + WT_OW0 + g * 256 * 256;
        jobs.K[4 + g]  = 256; jobs.N[4 + g] = 256;
    }
    jobs.W[7] = out_w; jobs.hi[7] = whi + WT_OUT; jobs.lo[7] = wlo + WT_OUT;
    jobs.K[7] = 768;   jobs.N[7] = 768;
    jobs.Ax = x; jobs.Axh = xh; jobs.Axl = xl; jobs.An = MD;
    prep_all_kernel<<<dim3(24, 24, 9), dim3(32, 8)>>>(jobs);

    // 1) h = x @ in_w + in_b
    {
        GemmArgs a{};
        a.Ah[0] = xh; a.Al[0] = xl; a.lda = DIM; a.K = 768;
        a.Bh[0] = whi + WT_IN; a.Bl[0] = wlo + WT_IN; a.bias[0] = in_b;
        a.Ch[0] = hh; a.Cl[0] = hl; a.ldc = DIM; a.qcols = 0;
        gemm_pp_kernel<true><<<dim3(6, 64, 1), 256, GEMM_SMEM>>>(a);
    }

    // 2) qkv (fused over groups; Q columns pre-scaled by 0.125*log2e)
    {
        GemmArgs a{};
        for (int g = 0; g < 3; ++g) {
            a.Ah[g] = hh + g * GDIM; a.Al[g] = hl + g * GDIM;
            a.Bh[g] = whi + WT_QKV0 + g * 768 * 256;
            a.Bl[g] = wlo + WT_QKV0 + g * 768 * 256;
            a.bias[g] = qkv_b[g];
            a.Ch[g] = qh + (size_t)g * MD; a.Cl[g] = ql + (size_t)g * MD;
        }
        a.lda = DIM; a.K = 256; a.ldc = DIM; a.qcols = 256;
        gemm_pp_kernel<true><<<dim3(6, 64, 3), 256, GEMM_SMEM>>>(a);
    }

    // 3) attention
    attn_tc_kernel<<<dim3(SEQ / 128, BATCH * 4, 3), 256, ATT_SMEM>>>(qh, ql, ah, al);

    // 4) out projection (fused, fp32 output into u)
    {
        GemmArgs a{};
        for (int g = 0; g < 3; ++g) {
            a.Ah[g] = ah + g * GDIM; a.Al[g] = al + g * GDIM;
            a.Bh[g] = whi + WT_OW0 + g * 256 * 256;
            a.Bl[g] = wlo + WT_OW0 + g * 256 * 256;
            a.bias[g] = ob[g];
            a.Cf[g] = u + g * GDIM;
        }
        a.lda = DIM; a.K = 256; a.ldc = DIM; a.qcols = 0;
        gemm_pp_kernel<false><<<dim3(2, 64, 3), 256, GEMM_SMEM>>>(a);
    }

    // 5) PDE (one launch, float4 channel tiles, split-plane output, 3 CTAs/SM)
    pde_all_kernel<<<dim3(BATCH * 64, 3), 256, PDE_SMEM>>>(u, uh, ul);

    // 6) out = u @ out_w + out_b
    {
        GemmArgs a{};
        a.Ah[0] = uh; a.Al[0] = ul; a.lda = DIM; a.K = 768;
        a.Bh[0] = whi + WT_OUT; a.Bl[0] = wlo + WT_OUT; a.bias[0] = out_b;
        a.Cf[0] = out; a.ldc = DIM; a.qcols = 0;
        gemm_pp_kernel<false><<<dim3(6, 64, 1), 256, GEMM_SMEM>>>(a);
    }
}